// round 13
// baseline (speedup 1.0000x reference)
#include <cuda_runtime.h>
#include <cuda_fp16.h>
#include <cuda_bf16.h>
#include <math.h>

#define Nn 50000
#define Ee 1600000
#define Fdim 512
#define Hdim 128
#define Cdim 40
#define EPSv 0.3f
#define AGG_BLOCKS 296   // 2 blocks/SM on 148 SMs: co-resident (launch_bounds enforced)

// ---------------- scratch (static device globals; no allocations) ----------
__device__ __align__(16) float g_raw[(size_t)Nn * Hdim];
// 4 fp16 h buffers: gemm->A, L0->B, L1->C, L2->D. No buffer is rewritten
// within the megakernel launch => no stale-L1 hazard.
__device__ __align__(16) __half2 g_h16A[(size_t)Nn * 64];
__device__ __align__(16) __half2 g_h16B[(size_t)Nn * 64];
__device__ __align__(16) __half2 g_h16C[(size_t)Nn * 64];
__device__ __align__(16) __half2 g_h16D[(size_t)Nn * 64];
__device__ float g_al[4][Nn];   // att slot l read by layer l, written by l-1
__device__ float g_ar[4][Nn];
__device__ float g_dis[Nn];
__device__ int   g_cnt[Nn];     // zeroed by k_scan each call (and at init)
__device__ int   g_rowptr[Nn + 1];
__device__ int   g_cursor[Nn];
__device__ __align__(16) int2 g_edge[Ee];
__device__ int   g_bar;         // megakernel barrier; zeroed by k_scan

__device__ __forceinline__ const __half2* h16_in(int l) {
    return l == 0 ? g_h16A : l == 1 ? g_h16B : l == 2 ? g_h16C : g_h16D;
}
__device__ __forceinline__ __half2* h16_out(int l) {
    return l == 0 ? g_h16B : l == 1 ? g_h16C : g_h16D;
}

// Per-element edge-id decode. Buffer has 4-byte elements (8-byte reads proved
// OOB in R1/R2). int32 ids are < Nn; float32 ids >= 2.0 have bit patterns
// >= 0x40000000 >> Nn, so this discriminates exactly per element.
__device__ __forceinline__ int dec_idx(int v) {
    return ((unsigned)v < (unsigned)Nn) ? v : (int)__int_as_float(v);
}

// ---------------- side stream + events (static init; capture stays clean) --
static cudaStream_t g_s2;
static cudaEvent_t g_evFork, g_evJoin;
namespace {
struct _StreamInit {
    _StreamInit() {
        cudaStreamCreateWithFlags(&g_s2, cudaStreamNonBlocking);
        cudaEventCreateWithFlags(&g_evFork, cudaEventDisableTiming);
        cudaEventCreateWithFlags(&g_evJoin, cudaEventDisableTiming);
    }
};
static _StreamInit _streamInit;
}

// ---------------- CSR build --------------------------------------------------
__global__ void k_hist(const int* __restrict__ ei, int e_total) {
    int e = blockIdx.x * blockDim.x + threadIdx.x;
    if (e < e_total) {
        int dst = dec_idx(ei[(size_t)Ee + e]);
        if ((unsigned)dst < (unsigned)Nn) atomicAdd(&g_cnt[dst], 1);
    }
}

// single-block fused scan: rowptr/cursor/dis + re-zero g_cnt + zero g_bar
__global__ void __launch_bounds__(1024) k_scan(int n) {
    __shared__ int s[1024];
    __shared__ int base_s;
    int tid = threadIdx.x;
    if (tid == 0) base_s = 0;
    __syncthreads();
    for (int c0 = 0; c0 < n; c0 += 1024) {
        int i = c0 + tid;
        int v = (i < n) ? g_cnt[i] : 0;
        s[tid] = v;
        __syncthreads();
#pragma unroll
        for (int off = 1; off < 1024; off <<= 1) {
            int t = (tid >= off) ? s[tid - off] : 0;
            __syncthreads();
            s[tid] += t;
            __syncthreads();
        }
        if (i < n) {
            int rp = base_s + s[tid] - v;   // exclusive prefix
            g_rowptr[i] = rp;
            g_cursor[i] = rp;
            g_dis[i] = rsqrtf((float)(v + 1));
            g_cnt[i] = 0;                   // ready for next call's hist
        }
        __syncthreads();
        if (tid == 0) base_s += s[1023];
        __syncthreads();
    }
    if (tid == 0) { g_rowptr[Nn] = Ee; g_bar = 0; }
}

__global__ void k_fill(const int* __restrict__ ei, int e_total) {
    int e = blockIdx.x * blockDim.x + threadIdx.x;
    if (e < e_total) {
        int src = dec_idx(ei[e]);
        int dst = dec_idx(ei[(size_t)Ee + e]);
        if ((unsigned)src < (unsigned)Nn && (unsigned)dst < (unsigned)Nn) {
            int pos = atomicAdd(&g_cursor[dst], 1);
            float nrm = g_dis[src] * g_dis[dst];
            g_edge[pos] = make_int2(src, __float_as_int(nrm));
        }
    }
}

// ---------------- GEMM1 via mma.sync bf16, double-buffered, fused att0 ------
#define LDA 40

#define LDSM4(R0, R1, R2, R3, ADDR)                                          \
    asm volatile("ldmatrix.sync.aligned.m8n8.x4.shared.b16 {%0,%1,%2,%3},[%4];" \
                 : "=r"(R0), "=r"(R1), "=r"(R2), "=r"(R3) : "r"(ADDR))

#define MMA_BF16(D, A, B)                                                    \
    asm volatile(                                                            \
        "mma.sync.aligned.m16n8k16.row.col.f32.bf16.bf16.f32 "               \
        "{%0,%1,%2,%3},{%4,%5,%6,%7},{%8,%9},{%0,%1,%2,%3};"                 \
        : "+f"((D)[0]), "+f"((D)[1]), "+f"((D)[2]), "+f"((D)[3])             \
        : "r"((A)[0]), "r"((A)[1]), "r"((A)[2]), "r"((A)[3]),                \
          "r"((B)[0]), "r"((B)[1]))

__global__ void __launch_bounds__(256) k_gemm1(const float* __restrict__ x,
                                               const float* __restrict__ W1,
                                               const float* __restrict__ b1,
                                               const float* __restrict__ attl,
                                               const float* __restrict__ attr) {
    __shared__ __nv_bfloat16 As[2][128 * LDA];
    __shared__ __nv_bfloat16 Bs[2][128 * LDA];
    __shared__ float sal[128], sar[128];
    int tid = threadIdx.x;
    int lane = tid & 31;
    int wid = tid >> 5;
    int wm = wid >> 2;
    int wn = wid & 3;
    int rowBlk = blockIdx.x * 128;

    float c[4][4][4];
#pragma unroll
    for (int tm = 0; tm < 4; tm++)
#pragma unroll
        for (int tn = 0; tn < 4; tn++)
#pragma unroll
            for (int q = 0; q < 4; q++) c[tm][tn][q] = 0.f;

    if (tid < 128) { sal[tid] = 0.f; sar[tid] = 0.f; }

    float4 ra[4], rb[4];

#pragma unroll
    for (int u = 0; u < 4; u++) {
        int s = tid + u * 256;
        int r = s >> 3, q = s & 7;
        int gr = rowBlk + r;
        ra[u] = (gr < Nn) ? *(const float4*)(x + (size_t)gr * Fdim + q * 4)
                          : make_float4(0.f, 0.f, 0.f, 0.f);
        rb[u] = *(const float4*)(W1 + (size_t)r * Fdim + q * 4);
    }
#pragma unroll
    for (int u = 0; u < 4; u++) {
        int s = tid + u * 256;
        int r = s >> 3, q = s & 7;
        __nv_bfloat162 a0 = __floats2bfloat162_rn(ra[u].x, ra[u].y);
        __nv_bfloat162 a1 = __floats2bfloat162_rn(ra[u].z, ra[u].w);
        uint2 pk; pk.x = *(unsigned*)&a0; pk.y = *(unsigned*)&a1;
        *(uint2*)&As[0][r * LDA + q * 4] = pk;
        __nv_bfloat162 b0 = __floats2bfloat162_rn(rb[u].x, rb[u].y);
        __nv_bfloat162 b1v = __floats2bfloat162_rn(rb[u].z, rb[u].w);
        uint2 qk; qk.x = *(unsigned*)&b0; qk.y = *(unsigned*)&b1v;
        *(uint2*)&Bs[0][r * LDA + q * 4] = qk;
    }
    __syncthreads();

    unsigned as0 = (unsigned)__cvta_generic_to_shared(&As[0][0]);
    unsigned bs0 = (unsigned)__cvta_generic_to_shared(&Bs[0][0]);
    const unsigned bufstride = 128 * LDA * 2;

#pragma unroll 1
    for (int kt = 0; kt < 16; kt++) {
        int buf = kt & 1;
        if (kt < 15) {
            int k0 = (kt + 1) * 32;
#pragma unroll
            for (int u = 0; u < 4; u++) {
                int s = tid + u * 256;
                int r = s >> 3, q = s & 7;
                int gr = rowBlk + r;
                ra[u] = (gr < Nn)
                            ? *(const float4*)(x + (size_t)gr * Fdim + k0 + q * 4)
                            : make_float4(0.f, 0.f, 0.f, 0.f);
                rb[u] = *(const float4*)(W1 + (size_t)r * Fdim + k0 + q * 4);
            }
        }

        unsigned as_base = as0 + buf * bufstride;
        unsigned bs_base = bs0 + buf * bufstride;
#pragma unroll
        for (int s16 = 0; s16 < 2; s16++) {
            int kb = s16 * 16;
            unsigned a[4][4];
            int arow = wm * 64 + (lane & 15);
            int acol = kb + ((lane >> 4) << 3);
#pragma unroll
            for (int tm = 0; tm < 4; tm++) {
                unsigned addr = as_base + ((arow + tm * 16) * LDA + acol) * 2;
                LDSM4(a[tm][0], a[tm][1], a[tm][2], a[tm][3], addr);
            }
            unsigned b[4][2];
#pragma unroll
            for (int g = 0; g < 2; g++) {
                int nrow = wn * 32 + g * 16 + ((lane >> 4) & 1) * 8 + (lane & 7);
                int ncol = kb + ((lane >> 3) & 1) * 8;
                unsigned addr = bs_base + (nrow * LDA + ncol) * 2;
                unsigned r0, r1, r2, r3;
                LDSM4(r0, r1, r2, r3, addr);
                b[2 * g][0] = r0; b[2 * g][1] = r1;
                b[2 * g + 1][0] = r2; b[2 * g + 1][1] = r3;
            }
#pragma unroll
            for (int tm = 0; tm < 4; tm++)
#pragma unroll
                for (int tn = 0; tn < 4; tn++) MMA_BF16(c[tm][tn], a[tm], b[tn]);
        }

        if (kt < 15) {
            int nbuf = buf ^ 1;
#pragma unroll
            for (int u = 0; u < 4; u++) {
                int s = tid + u * 256;
                int r = s >> 3, q = s & 7;
                __nv_bfloat162 a0 = __floats2bfloat162_rn(ra[u].x, ra[u].y);
                __nv_bfloat162 a1 = __floats2bfloat162_rn(ra[u].z, ra[u].w);
                uint2 pk; pk.x = *(unsigned*)&a0; pk.y = *(unsigned*)&a1;
                *(uint2*)&As[nbuf][r * LDA + q * 4] = pk;
                __nv_bfloat162 b0 = __floats2bfloat162_rn(rb[u].x, rb[u].y);
                __nv_bfloat162 b1v = __floats2bfloat162_rn(rb[u].z, rb[u].w);
                uint2 qk; qk.x = *(unsigned*)&b0; qk.y = *(unsigned*)&b1v;
                *(uint2*)&Bs[nbuf][r * LDA + q * 4] = qk;
            }
        }
        __syncthreads();
    }

    // epilogue: bias + relu -> g_raw + g_h16A; fused layer-0 att reduction
    int r_base = rowBlk + wm * 64 + (lane >> 2);
#pragma unroll
    for (int tm = 0; tm < 4; tm++) {
#pragma unroll
        for (int half = 0; half < 2; half++) {
            int row = r_base + tm * 16 + half * 8;
            float pa = 0.f, pr = 0.f;
#pragma unroll
            for (int tn = 0; tn < 4; tn++) {
                int n = wn * 32 + tn * 8 + (lane & 3) * 2;
                float2 bv = *(const float2*)(b1 + n);
                float o0 = fmaxf(c[tm][tn][2 * half + 0] + bv.x, 0.f);
                float o1 = fmaxf(c[tm][tn][2 * half + 1] + bv.y, 0.f);
                float2 Lv = *(const float2*)(attl + n);
                float2 Rv = *(const float2*)(attr + n);
                pa += o0 * Lv.x + o1 * Lv.y;
                pr += o0 * Rv.x + o1 * Rv.y;
                if (row < Nn) {
                    *(float2*)(g_raw + (size_t)row * Hdim + n) =
                        make_float2(o0, o1);
                    g_h16A[(size_t)row * 64 + (n >> 1)] =
                        __floats2half2_rn(o0, o1);
                }
            }
            pa += __shfl_xor_sync(0xffffffffu, pa, 1);
            pa += __shfl_xor_sync(0xffffffffu, pa, 2);
            pr += __shfl_xor_sync(0xffffffffu, pr, 1);
            pr += __shfl_xor_sync(0xffffffffu, pr, 2);
            if ((lane & 3) == 0) {
                int rl = wm * 64 + tm * 16 + half * 8 + (lane >> 2);
                atomicAdd(&sal[rl], pa);
                atomicAdd(&sar[rl], pr);
            }
        }
    }
    __syncthreads();
    if (tid < 128) {
        int gr = rowBlk + tid;
        if (gr < Nn) { g_al[0][gr] = sal[tid]; g_ar[0][gr] = sar[tid]; }
    }
}

// ---------------- persistent megakernel: 4 agg layers + fused att/out -------
// __launch_bounds__(256, 2): force >=2 blocks/SM so all 296 blocks are
// co-resident in wave 1 (required for the grid-wide spin barrier).
__global__ void __launch_bounds__(256, 2) k_agg_mega(
    const float* __restrict__ attl, const float* __restrict__ attr,
    const float* __restrict__ W2, const float* __restrict__ b2,
    float* __restrict__ out) {
    __shared__ float slog[8][40];
    __shared__ int2 sedge[8][32];
    int lane = threadIdx.x & 31;
    int lw = threadIdx.x >> 5;
    int stride = gridDim.x * 8;

#pragma unroll 1
    for (int l = 0; l < 4; l++) {
        const uint2* h16v = (const uint2*)h16_in(l);
        uint2* h16o = (l < 3) ? (uint2*)h16_out(l) : (uint2*)0;
        const float* alr = g_al[l];
        const float* arr = g_ar[l];
        const float* aln = attl + ((l < 3) ? (l + 1) * Hdim : 0);
        const float* arn = attr + ((l < 3) ? (l + 1) * Hdim : 0);

        for (int gw = blockIdx.x * 8 + lw; gw < Nn; gw += stride) {
            int start = g_rowptr[gw];
            int end = g_rowptr[gw + 1];
            float ar_i = arr[gw];
            float d = g_dis[gw];
            uint2 hvs = h16v[(size_t)gw * 32 + lane];
            float4 rw = ((const float4*)g_raw)[(size_t)gw * 32 + lane];

            float4 acc = make_float4(0.f, 0.f, 0.f, 0.f);
            for (int base = start; base < end; base += 32) {
                int m = min(32, end - base);
                __syncwarp();
                if (lane < m) {
                    int2 ed = g_edge[base + lane];
                    float cf = tanhf(alr[ed.x] + ar_i) * __int_as_float(ed.y);
                    sedge[lw][lane] = make_int2(ed.x, __float_as_int(cf));
                }
                __syncwarp();
#pragma unroll 4
                for (int j = 0; j < m; j++) {
                    int2 ec = sedge[lw][j];
                    float c = __int_as_float(ec.y);
                    uint2 hv = h16v[(size_t)ec.x * 32 + lane];
                    float2 f0 = __half22float2(*(__half2*)&hv.x);
                    float2 f1 = __half22float2(*(__half2*)&hv.y);
                    acc.x = fmaf(c, f0.x, acc.x);
                    acc.y = fmaf(c, f0.y, acc.y);
                    acc.z = fmaf(c, f1.x, acc.z);
                    acc.w = fmaf(c, f1.y, acc.w);
                }
            }

            float cs = tanhf(alr[gw] + ar_i) * d * d;
            float2 s0 = __half22float2(*(__half2*)&hvs.x);
            float2 s1 = __half22float2(*(__half2*)&hvs.y);
            acc.x += cs * s0.x + EPSv * rw.x;
            acc.y += cs * s0.y + EPSv * rw.y;
            acc.z += cs * s1.x + EPSv * rw.z;
            acc.w += cs * s1.y + EPSv * rw.w;

            if (l < 3) {
                __half2 hh[2];
                hh[0] = __floats2half2_rn(acc.x, acc.y);
                hh[1] = __floats2half2_rn(acc.z, acc.w);
                h16o[(size_t)gw * 32 + lane] = *(uint2*)hh;

                float4 Lv = ((const float4*)aln)[lane];
                float4 Rv = ((const float4*)arn)[lane];
                float pa = acc.x * Lv.x + acc.y * Lv.y + acc.z * Lv.z + acc.w * Lv.w;
                float pr = acc.x * Rv.x + acc.y * Rv.y + acc.z * Rv.z + acc.w * Rv.w;
#pragma unroll
                for (int off = 16; off; off >>= 1) {
                    pa += __shfl_xor_sync(0xffffffffu, pa, off);
                    pr += __shfl_xor_sync(0xffffffffu, pr, off);
                }
                if (lane == 0) { g_al[l + 1][gw] = pa; g_ar[l + 1][gw] = pr; }
            } else {
#pragma unroll
                for (int c = 0; c < Cdim; c++) {
                    float4 wv = *(const float4*)(W2 + (size_t)c * Hdim + lane * 4);
                    float p = acc.x * wv.x + acc.y * wv.y + acc.z * wv.z + acc.w * wv.w;
                    p += __shfl_down_sync(0xffffffffu, p, 16);
                    p += __shfl_down_sync(0xffffffffu, p, 8);
                    p += __shfl_down_sync(0xffffffffu, p, 4);
                    p += __shfl_down_sync(0xffffffffu, p, 2);
                    p += __shfl_down_sync(0xffffffffu, p, 1);
                    if (lane == 0) slog[lw][c] = p + b2[c];
                }
                __syncwarp();
                float m = -1e30f;
                for (int c = lane; c < Cdim; c += 32) m = fmaxf(m, slog[lw][c]);
#pragma unroll
                for (int o = 16; o; o >>= 1)
                    m = fmaxf(m, __shfl_xor_sync(0xffffffffu, m, o));
                float s = 0.f;
                for (int c = lane; c < Cdim; c += 32) s += expf(slog[lw][c] - m);
#pragma unroll
                for (int o = 16; o; o >>= 1) s += __shfl_xor_sync(0xffffffffu, s, o);
                float lse = m + logf(s);
                for (int c = lane; c < Cdim; c += 32)
                    out[(size_t)gw * Cdim + c] = slog[lw][c] - lse;
                __syncwarp();
            }
        }

        // device-wide barrier between layers
        if (l < 3) {
            __threadfence();
            __syncthreads();
            if (threadIdx.x == 0) {
                atomicAdd(&g_bar, 1);
                int target = (l + 1) * gridDim.x;
                while (*((volatile int*)&g_bar) < target) { __nanosleep(64); }
            }
            __syncthreads();
            __threadfence();
        }
    }
}

// ---------------- launch: 5 launches total, CSR || GEMM fork ---------------
extern "C" void kernel_launch(void* const* d_in, const int* in_sizes, int n_in,
                              void* d_out, int out_size) {
    const float* x = (const float*)d_in[0];
    const int* ei = (const int*)d_in[1];
    const float* W1 = (const float*)d_in[2];
    const float* b1 = (const float*)d_in[3];
    const float* W2 = (const float*)d_in[4];
    const float* b2 = (const float*)d_in[5];
    const float* attl = (const float*)d_in[6];
    const float* attr = (const float*)d_in[7];
    float* out = (float*)d_out;

    const int NBe = (Ee + 255) / 256;

    cudaEventRecord(g_evFork, 0);
    cudaStreamWaitEvent(g_s2, g_evFork, 0);

    // main stream: CSR build (g_cnt pre-zeroed by previous call's k_scan)
    k_hist<<<NBe, 256>>>(ei, Ee);                                 // 1
    k_scan<<<1, 1024>>>(Nn);                                      // 2
    k_fill<<<NBe, 256>>>(ei, Ee);                                 // 3

    // side stream: GEMM + fused layer-0 att (runs parallel from fork)
    k_gemm1<<<(Nn + 127) / 128, 256, 0, g_s2>>>(x, W1, b1, attl, attr);  // 4

    cudaEventRecord(g_evJoin, g_s2);
    cudaStreamWaitEvent(0, g_evJoin, 0);

    // persistent megakernel: all 4 layers + logits + log_softmax
    k_agg_mega<<<AGG_BLOCKS, 256>>>(attl, attr, W2, b2, out);     // 5
}

// round 14
// speedup vs baseline: 1.5817x; 1.5817x over previous
#include <cuda_runtime.h>
#include <cuda_fp16.h>
#include <cuda_bf16.h>
#include <math.h>

#define Nn 50000
#define Ee 1600000
#define Fdim 512
#define Hdim 128
#define Cdim 40
#define EPSv 0.3f

// ---------------- scratch (static device globals; no allocations) ----------
__device__ __align__(16) float g_raw[(size_t)Nn * Hdim];
__device__ __align__(16) __half2 g_h16A[(size_t)Nn * 64];
__device__ __align__(16) __half2 g_h16B[(size_t)Nn * 64];
__device__ float g_al[2][Nn];
__device__ float g_ar[2][Nn];
__device__ float g_dis[Nn];
__device__ int   g_cnt[Nn];     // zero at load; re-zeroed by k_scan3 each call
__device__ int   g_rowptr[Nn + 1];
__device__ int   g_cursor[Nn];
__device__ __align__(16) int2 g_edge[Ee];
__device__ int   g_bsum[256];

__device__ __forceinline__ __half2* h16_sel(int s) {
    return s == 0 ? g_h16A : g_h16B;
}

// Per-element edge-id decode: buffer has 4-byte elements; int32 ids < Nn,
// float32 ids >= 2.0 have bit patterns >= 0x40000000 >> Nn. Exact per element.
__device__ __forceinline__ int dec_idx(int v) {
    return ((unsigned)v < (unsigned)Nn) ? v : (int)__int_as_float(v);
}

// ---------------- side stream + events (static init; capture stays clean) --
static cudaStream_t g_s2;
static cudaEvent_t g_evFork, g_evJoin;
namespace {
struct _StreamInit {
    _StreamInit() {
        cudaStreamCreateWithFlags(&g_s2, cudaStreamNonBlocking);
        cudaEventCreateWithFlags(&g_evFork, cudaEventDisableTiming);
        cudaEventCreateWithFlags(&g_evJoin, cudaEventDisableTiming);
    }
};
static _StreamInit _streamInit;
}

// ---------------- CSR build --------------------------------------------------
__global__ void k_hist(const int* __restrict__ ei, int e_total) {
    int e = blockIdx.x * blockDim.x + threadIdx.x;
    if (e < e_total) {
        int dst = dec_idx(ei[(size_t)Ee + e]);
        if ((unsigned)dst < (unsigned)Nn) atomicAdd(&g_cnt[dst], 1);
    }
}

__global__ void k_scan1(int n) {
    __shared__ int s[256];
    int tid = threadIdx.x;
    int i = blockIdx.x * 256 + tid;
    int v = (i < n) ? g_cnt[i] : 0;
    s[tid] = v;
    __syncthreads();
#pragma unroll
    for (int off = 1; off < 256; off <<= 1) {
        int t = (tid >= off) ? s[tid - off] : 0;
        __syncthreads();
        s[tid] += t;
        __syncthreads();
    }
    if (i < n) g_rowptr[i] = s[tid] - v;
    if (tid == 255) g_bsum[blockIdx.x] = s[255];
}

// block-sum scan (redundant per block) + rowptr/cursor/dis + re-zero g_cnt
__global__ void k_scan3(int n, int nblocks) {
    __shared__ int s[256];
    int tid = threadIdx.x;
    int v = (tid < nblocks) ? g_bsum[tid] : 0;
    s[tid] = v;
    __syncthreads();
#pragma unroll
    for (int off = 1; off < 256; off <<= 1) {
        int t = (tid >= off) ? s[tid - off] : 0;
        __syncthreads();
        s[tid] += t;
        __syncthreads();
    }
    int boff = (blockIdx.x == 0) ? 0 : s[blockIdx.x - 1];
    int i = blockIdx.x * 256 + tid;
    if (i < n) {
        int rp = g_rowptr[i] + boff;
        g_rowptr[i] = rp;
        g_cursor[i] = rp;
        g_dis[i] = rsqrtf((float)(g_cnt[i] + 1));
        g_cnt[i] = 0;   // ready for next call's k_hist
    }
    if (i == 0) g_rowptr[Nn] = Ee;
}

__global__ void k_fill(const int* __restrict__ ei, int e_total) {
    int e = blockIdx.x * blockDim.x + threadIdx.x;
    if (e < e_total) {
        int src = dec_idx(ei[e]);
        int dst = dec_idx(ei[(size_t)Ee + e]);
        if ((unsigned)src < (unsigned)Nn && (unsigned)dst < (unsigned)Nn) {
            int pos = atomicAdd(&g_cursor[dst], 1);
            float nrm = g_dis[src] * g_dis[dst];
            g_edge[pos] = make_int2(src, __float_as_int(nrm));
        }
    }
}

// ---------------- GEMM1 via mma.sync bf16, double-buffered, fused att0 ------
#define LDA 40

#define LDSM4(R0, R1, R2, R3, ADDR)                                          \
    asm volatile("ldmatrix.sync.aligned.m8n8.x4.shared.b16 {%0,%1,%2,%3},[%4];" \
                 : "=r"(R0), "=r"(R1), "=r"(R2), "=r"(R3) : "r"(ADDR))

#define MMA_BF16(D, A, B)                                                    \
    asm volatile(                                                            \
        "mma.sync.aligned.m16n8k16.row.col.f32.bf16.bf16.f32 "               \
        "{%0,%1,%2,%3},{%4,%5,%6,%7},{%8,%9},{%0,%1,%2,%3};"                 \
        : "+f"((D)[0]), "+f"((D)[1]), "+f"((D)[2]), "+f"((D)[3])             \
        : "r"((A)[0]), "r"((A)[1]), "r"((A)[2]), "r"((A)[3]),                \
          "r"((B)[0]), "r"((B)[1]))

__global__ void __launch_bounds__(256) k_gemm1(const float* __restrict__ x,
                                               const float* __restrict__ W1,
                                               const float* __restrict__ b1,
                                               const float* __restrict__ attl,
                                               const float* __restrict__ attr) {
    __shared__ __nv_bfloat16 As[2][128 * LDA];
    __shared__ __nv_bfloat16 Bs[2][128 * LDA];
    __shared__ float sal[128], sar[128];
    int tid = threadIdx.x;
    int lane = tid & 31;
    int wid = tid >> 5;
    int wm = wid >> 2;
    int wn = wid & 3;
    int rowBlk = blockIdx.x * 128;

    float c[4][4][4];
#pragma unroll
    for (int tm = 0; tm < 4; tm++)
#pragma unroll
        for (int tn = 0; tn < 4; tn++)
#pragma unroll
            for (int q = 0; q < 4; q++) c[tm][tn][q] = 0.f;

    if (tid < 128) { sal[tid] = 0.f; sar[tid] = 0.f; }

    float4 ra[4], rb[4];

#pragma unroll
    for (int u = 0; u < 4; u++) {
        int s = tid + u * 256;
        int r = s >> 3, q = s & 7;
        int gr = rowBlk + r;
        ra[u] = (gr < Nn) ? *(const float4*)(x + (size_t)gr * Fdim + q * 4)
                          : make_float4(0.f, 0.f, 0.f, 0.f);
        rb[u] = *(const float4*)(W1 + (size_t)r * Fdim + q * 4);
    }
#pragma unroll
    for (int u = 0; u < 4; u++) {
        int s = tid + u * 256;
        int r = s >> 3, q = s & 7;
        __nv_bfloat162 a0 = __floats2bfloat162_rn(ra[u].x, ra[u].y);
        __nv_bfloat162 a1 = __floats2bfloat162_rn(ra[u].z, ra[u].w);
        uint2 pk; pk.x = *(unsigned*)&a0; pk.y = *(unsigned*)&a1;
        *(uint2*)&As[0][r * LDA + q * 4] = pk;
        __nv_bfloat162 b0 = __floats2bfloat162_rn(rb[u].x, rb[u].y);
        __nv_bfloat162 b1v = __floats2bfloat162_rn(rb[u].z, rb[u].w);
        uint2 qk; qk.x = *(unsigned*)&b0; qk.y = *(unsigned*)&b1v;
        *(uint2*)&Bs[0][r * LDA + q * 4] = qk;
    }
    __syncthreads();

    unsigned as0 = (unsigned)__cvta_generic_to_shared(&As[0][0]);
    unsigned bs0 = (unsigned)__cvta_generic_to_shared(&Bs[0][0]);
    const unsigned bufstride = 128 * LDA * 2;

#pragma unroll 1
    for (int kt = 0; kt < 16; kt++) {
        int buf = kt & 1;
        if (kt < 15) {
            int k0 = (kt + 1) * 32;
#pragma unroll
            for (int u = 0; u < 4; u++) {
                int s = tid + u * 256;
                int r = s >> 3, q = s & 7;
                int gr = rowBlk + r;
                ra[u] = (gr < Nn)
                            ? *(const float4*)(x + (size_t)gr * Fdim + k0 + q * 4)
                            : make_float4(0.f, 0.f, 0.f, 0.f);
                rb[u] = *(const float4*)(W1 + (size_t)r * Fdim + k0 + q * 4);
            }
        }

        unsigned as_base = as0 + buf * bufstride;
        unsigned bs_base = bs0 + buf * bufstride;
#pragma unroll
        for (int s16 = 0; s16 < 2; s16++) {
            int kb = s16 * 16;
            unsigned a[4][4];
            int arow = wm * 64 + (lane & 15);
            int acol = kb + ((lane >> 4) << 3);
#pragma unroll
            for (int tm = 0; tm < 4; tm++) {
                unsigned addr = as_base + ((arow + tm * 16) * LDA + acol) * 2;
                LDSM4(a[tm][0], a[tm][1], a[tm][2], a[tm][3], addr);
            }
            unsigned b[4][2];
#pragma unroll
            for (int g = 0; g < 2; g++) {
                int nrow = wn * 32 + g * 16 + ((lane >> 4) & 1) * 8 + (lane & 7);
                int ncol = kb + ((lane >> 3) & 1) * 8;
                unsigned addr = bs_base + (nrow * LDA + ncol) * 2;
                unsigned r0, r1, r2, r3;
                LDSM4(r0, r1, r2, r3, addr);
                b[2 * g][0] = r0; b[2 * g][1] = r1;
                b[2 * g + 1][0] = r2; b[2 * g + 1][1] = r3;
            }
#pragma unroll
            for (int tm = 0; tm < 4; tm++)
#pragma unroll
                for (int tn = 0; tn < 4; tn++) MMA_BF16(c[tm][tn], a[tm], b[tn]);
        }

        if (kt < 15) {
            int nbuf = buf ^ 1;
#pragma unroll
            for (int u = 0; u < 4; u++) {
                int s = tid + u * 256;
                int r = s >> 3, q = s & 7;
                __nv_bfloat162 a0 = __floats2bfloat162_rn(ra[u].x, ra[u].y);
                __nv_bfloat162 a1 = __floats2bfloat162_rn(ra[u].z, ra[u].w);
                uint2 pk; pk.x = *(unsigned*)&a0; pk.y = *(unsigned*)&a1;
                *(uint2*)&As[nbuf][r * LDA + q * 4] = pk;
                __nv_bfloat162 b0 = __floats2bfloat162_rn(rb[u].x, rb[u].y);
                __nv_bfloat162 b1v = __floats2bfloat162_rn(rb[u].z, rb[u].w);
                uint2 qk; qk.x = *(unsigned*)&b0; qk.y = *(unsigned*)&b1v;
                *(uint2*)&Bs[nbuf][r * LDA + q * 4] = qk;
            }
        }
        __syncthreads();
    }

    // epilogue: bias + relu -> g_raw + g_h16A; fused layer-0 att reduction
    int r_base = rowBlk + wm * 64 + (lane >> 2);
#pragma unroll
    for (int tm = 0; tm < 4; tm++) {
#pragma unroll
        for (int half = 0; half < 2; half++) {
            int row = r_base + tm * 16 + half * 8;
            float pa = 0.f, pr = 0.f;
#pragma unroll
            for (int tn = 0; tn < 4; tn++) {
                int n = wn * 32 + tn * 8 + (lane & 3) * 2;
                float2 bv = *(const float2*)(b1 + n);
                float o0 = fmaxf(c[tm][tn][2 * half + 0] + bv.x, 0.f);
                float o1 = fmaxf(c[tm][tn][2 * half + 1] + bv.y, 0.f);
                float2 Lv = *(const float2*)(attl + n);
                float2 Rv = *(const float2*)(attr + n);
                pa += o0 * Lv.x + o1 * Lv.y;
                pr += o0 * Rv.x + o1 * Rv.y;
                if (row < Nn) {
                    *(float2*)(g_raw + (size_t)row * Hdim + n) =
                        make_float2(o0, o1);
                    g_h16A[(size_t)row * 64 + (n >> 1)] =
                        __floats2half2_rn(o0, o1);
                }
            }
            pa += __shfl_xor_sync(0xffffffffu, pa, 1);
            pa += __shfl_xor_sync(0xffffffffu, pa, 2);
            pr += __shfl_xor_sync(0xffffffffu, pr, 1);
            pr += __shfl_xor_sync(0xffffffffu, pr, 2);
            if ((lane & 3) == 0) {
                int rl = wm * 64 + tm * 16 + half * 8 + (lane >> 2);
                atomicAdd(&sal[rl], pa);
                atomicAdd(&sar[rl], pr);
            }
        }
    }
    __syncthreads();
    if (tid < 128) {
        int gr = rowBlk + tid;
        if (gr < Nn) { g_al[0][gr] = sal[tid]; g_ar[0][gr] = sar[tid]; }
    }
}

// ---------------- aggregation: warp/node, smem-staged coef, fused att/out ---
__global__ void k_agg(int h16in_sel, int h16out_sel, int rd, int wr,
                      const float* __restrict__ attl_next,
                      const float* __restrict__ attr_next, int write_att,
                      const float* __restrict__ W2, const float* __restrict__ b2,
                      float* __restrict__ out, int write_out) {
    __shared__ float slog[8][40];
    __shared__ int2 sedge[8][32];
    int gw = (blockIdx.x * blockDim.x + threadIdx.x) >> 5;
    int lane = threadIdx.x & 31;
    int lw = threadIdx.x >> 5;
    if (gw >= Nn) return;
    const uint2* h16v = (const uint2*)h16_sel(h16in_sel);
    const float* alr = g_al[rd];

    float4 acc = make_float4(0.f, 0.f, 0.f, 0.f);
    float ar_i = g_ar[rd][gw];
    int start = g_rowptr[gw];
    int end = g_rowptr[gw + 1];

    for (int base = start; base < end; base += 32) {
        int m = min(32, end - base);
        __syncwarp();
        if (lane < m) {
            int2 ed = g_edge[base + lane];
            float cf = tanhf(alr[ed.x] + ar_i) * __int_as_float(ed.y);
            sedge[lw][lane] = make_int2(ed.x, __float_as_int(cf));
        }
        __syncwarp();
#pragma unroll 4
        for (int j = 0; j < m; j++) {
            int2 ec = sedge[lw][j];
            float c = __int_as_float(ec.y);
            uint2 hv = h16v[(size_t)ec.x * 32 + lane];
            float2 f0 = __half22float2(*(__half2*)&hv.x);
            float2 f1 = __half22float2(*(__half2*)&hv.y);
            acc.x = fmaf(c, f0.x, acc.x);
            acc.y = fmaf(c, f0.y, acc.y);
            acc.z = fmaf(c, f1.x, acc.z);
            acc.w = fmaf(c, f1.y, acc.w);
        }
    }

    // self loop (fp16 state) + eps*raw (fp32)
    float d = g_dis[gw];
    float cs = tanhf(alr[gw] + ar_i) * d * d;
    uint2 hvs = h16v[(size_t)gw * 32 + lane];
    float2 s0 = __half22float2(*(__half2*)&hvs.x);
    float2 s1 = __half22float2(*(__half2*)&hvs.y);
    float4 rw = ((const float4*)g_raw)[(size_t)gw * 32 + lane];
    acc.x += cs * s0.x + EPSv * rw.x;
    acc.y += cs * s0.y + EPSv * rw.y;
    acc.z += cs * s1.x + EPSv * rw.z;
    acc.w += cs * s1.y + EPSv * rw.w;

    if (!write_out) {
        __half2 hh[2];
        hh[0] = __floats2half2_rn(acc.x, acc.y);
        hh[1] = __floats2half2_rn(acc.z, acc.w);
        ((uint2*)h16_sel(h16out_sel))[(size_t)gw * 32 + lane] = *(uint2*)hh;
    }

    if (write_att) {
        float4 Lv = ((const float4*)attl_next)[lane];
        float4 Rv = ((const float4*)attr_next)[lane];
        float pa = acc.x * Lv.x + acc.y * Lv.y + acc.z * Lv.z + acc.w * Lv.w;
        float pr = acc.x * Rv.x + acc.y * Rv.y + acc.z * Rv.z + acc.w * Rv.w;
#pragma unroll
        for (int off = 16; off; off >>= 1) {
            pa += __shfl_xor_sync(0xffffffffu, pa, off);
            pr += __shfl_xor_sync(0xffffffffu, pr, off);
        }
        if (lane == 0) { g_al[wr][gw] = pa; g_ar[wr][gw] = pr; }
    }

    if (write_out) {
#pragma unroll
        for (int c = 0; c < Cdim; c++) {
            float4 wv = *(const float4*)(W2 + (size_t)c * Hdim + lane * 4);
            float p = acc.x * wv.x + acc.y * wv.y + acc.z * wv.z + acc.w * wv.w;
            p += __shfl_down_sync(0xffffffffu, p, 16);
            p += __shfl_down_sync(0xffffffffu, p, 8);
            p += __shfl_down_sync(0xffffffffu, p, 4);
            p += __shfl_down_sync(0xffffffffu, p, 2);
            p += __shfl_down_sync(0xffffffffu, p, 1);
            if (lane == 0) slog[lw][c] = p + b2[c];
        }
        __syncwarp();
        float m = -1e30f;
        for (int c = lane; c < Cdim; c += 32) m = fmaxf(m, slog[lw][c]);
#pragma unroll
        for (int o = 16; o; o >>= 1)
            m = fmaxf(m, __shfl_xor_sync(0xffffffffu, m, o));
        float s = 0.f;
        for (int c = lane; c < Cdim; c += 32) s += expf(slog[lw][c] - m);
#pragma unroll
        for (int o = 16; o; o >>= 1) s += __shfl_xor_sync(0xffffffffu, s, o);
        float lse = m + logf(s);
        for (int c = lane; c < Cdim; c += 32)
            out[(size_t)gw * Cdim + c] = slog[lw][c] - lse;
    }
}

// ---------------- launch: CSR || GEMM(+att0) fork, 4x agg, 9 launches -------
extern "C" void kernel_launch(void* const* d_in, const int* in_sizes, int n_in,
                              void* d_out, int out_size) {
    const float* x = (const float*)d_in[0];
    const int* ei = (const int*)d_in[1];
    const float* W1 = (const float*)d_in[2];
    const float* b1 = (const float*)d_in[3];
    const float* W2 = (const float*)d_in[4];
    const float* b2 = (const float*)d_in[5];
    const float* attl = (const float*)d_in[6];
    const float* attr = (const float*)d_in[7];
    float* out = (float*)d_out;

    const int NBn = (Nn + 255) / 256;
    const int NBe = (Ee + 255) / 256;
    const int NBw = (Nn * 32 + 255) / 256;

    cudaEventRecord(g_evFork, 0);
    cudaStreamWaitEvent(g_s2, g_evFork, 0);

    // side stream: GEMM with fused layer-0 att
    k_gemm1<<<(Nn + 127) / 128, 256, 0, g_s2>>>(x, W1, b1, attl, attr);

    // main stream: CSR build chain (g_cnt pre-zeroed by prior call's scan3)
    k_hist<<<NBe, 256>>>(ei, Ee);
    k_scan1<<<NBn, 256>>>(Nn);
    k_scan3<<<NBn, 256>>>(Nn, NBn);
    k_fill<<<NBe, 256>>>(ei, Ee);

    cudaEventRecord(g_evJoin, g_s2);
    cudaStreamWaitEvent(0, g_evJoin, 0);

    int h16in = 0;
    for (int l = 0; l < 4; l++) {
        int rd = l & 1;
        int wr = 1 - rd;
        int h16out = 1 - h16in;
        const float* al_n = (l < 3) ? attl + (l + 1) * Hdim : attl;
        const float* ar_n = (l < 3) ? attr + (l + 1) * Hdim : attr;
        k_agg<<<NBw, 256>>>(h16in, h16out, rd, wr, al_n, ar_n, l < 3 ? 1 : 0,
                            W2, b2, out, l == 3 ? 1 : 0);
        h16in = h16out;
    }
}

// round 15
// speedup vs baseline: 1.5862x; 1.0028x over previous
#include <cuda_runtime.h>
#include <cuda_fp16.h>
#include <cuda_bf16.h>
#include <math.h>

#define Nn 50000
#define Ee 1600000
#define Fdim 512
#define Hdim 128
#define Cdim 40
#define EPSv 0.3f

// ---------------- scratch (static device globals; no allocations) ----------
__device__ __align__(16) float g_raw[(size_t)Nn * Hdim];
__device__ __align__(16) __half2 g_h16A[(size_t)Nn * 64];
__device__ __align__(16) __half2 g_h16B[(size_t)Nn * 64];
__device__ float g_al[2][Nn];
__device__ float g_ar[2][Nn];
__device__ float g_dis[Nn];
__device__ int   g_cnt[Nn];     // zero at load; re-zeroed by k_scan3 each call
__device__ int   g_rowptr[Nn + 1];
__device__ int   g_cursor[Nn];
__device__ __align__(16) int2 g_edge[Ee];
__device__ int   g_bsum[256];

__device__ __forceinline__ __half2* h16_sel(int s) {
    return s == 0 ? g_h16A : g_h16B;
}

// Per-element edge-id decode: buffer has 4-byte elements; int32 ids < Nn,
// float32 ids >= 2.0 have bit patterns >= 0x40000000 >> Nn. Exact per element.
__device__ __forceinline__ int dec_idx(int v) {
    return ((unsigned)v < (unsigned)Nn) ? v : (int)__int_as_float(v);
}

// ---------------- side stream + events (static init; capture stays clean) --
static cudaStream_t g_s2;
static cudaEvent_t g_evFork, g_evJoin;
namespace {
struct _StreamInit {
    _StreamInit() {
        cudaStreamCreateWithFlags(&g_s2, cudaStreamNonBlocking);
        cudaEventCreateWithFlags(&g_evFork, cudaEventDisableTiming);
        cudaEventCreateWithFlags(&g_evJoin, cudaEventDisableTiming);
    }
};
static _StreamInit _streamInit;
}

// ---------------- CSR build --------------------------------------------------
__global__ void k_hist(const int* __restrict__ ei, int e_total) {
    int e = blockIdx.x * blockDim.x + threadIdx.x;
    if (e < e_total) {
        int dst = dec_idx(ei[(size_t)Ee + e]);
        if ((unsigned)dst < (unsigned)Nn) atomicAdd(&g_cnt[dst], 1);
    }
}

__global__ void k_scan1(int n) {
    __shared__ int s[256];
    int tid = threadIdx.x;
    int i = blockIdx.x * 256 + tid;
    int v = (i < n) ? g_cnt[i] : 0;
    s[tid] = v;
    __syncthreads();
#pragma unroll
    for (int off = 1; off < 256; off <<= 1) {
        int t = (tid >= off) ? s[tid - off] : 0;
        __syncthreads();
        s[tid] += t;
        __syncthreads();
    }
    if (i < n) g_rowptr[i] = s[tid] - v;
    if (tid == 255) g_bsum[blockIdx.x] = s[255];
}

// block-sum scan (redundant per block) + rowptr/cursor/dis + re-zero g_cnt
__global__ void k_scan3(int n, int nblocks) {
    __shared__ int s[256];
    int tid = threadIdx.x;
    int v = (tid < nblocks) ? g_bsum[tid] : 0;
    s[tid] = v;
    __syncthreads();
#pragma unroll
    for (int off = 1; off < 256; off <<= 1) {
        int t = (tid >= off) ? s[tid - off] : 0;
        __syncthreads();
        s[tid] += t;
        __syncthreads();
    }
    int boff = (blockIdx.x == 0) ? 0 : s[blockIdx.x - 1];
    int i = blockIdx.x * 256 + tid;
    if (i < n) {
        int rp = g_rowptr[i] + boff;
        g_rowptr[i] = rp;
        g_cursor[i] = rp;
        g_dis[i] = rsqrtf((float)(g_cnt[i] + 1));
        g_cnt[i] = 0;   // ready for next call's k_hist
    }
    if (i == 0) g_rowptr[Nn] = Ee;
}

__global__ void k_fill(const int* __restrict__ ei, int e_total) {
    int e = blockIdx.x * blockDim.x + threadIdx.x;
    if (e < e_total) {
        int src = dec_idx(ei[e]);
        int dst = dec_idx(ei[(size_t)Ee + e]);
        if ((unsigned)src < (unsigned)Nn && (unsigned)dst < (unsigned)Nn) {
            int pos = atomicAdd(&g_cursor[dst], 1);
            float nrm = g_dis[src] * g_dis[dst];
            g_edge[pos] = make_int2(src, __float_as_int(nrm));
        }
    }
}

// ---------------- GEMM1 via mma.sync bf16, double-buffered, fused att0 ------
#define LDA 40

#define LDSM4(R0, R1, R2, R3, ADDR)                                          \
    asm volatile("ldmatrix.sync.aligned.m8n8.x4.shared.b16 {%0,%1,%2,%3},[%4];" \
                 : "=r"(R0), "=r"(R1), "=r"(R2), "=r"(R3) : "r"(ADDR))

#define MMA_BF16(D, A, B)                                                    \
    asm volatile(                                                            \
        "mma.sync.aligned.m16n8k16.row.col.f32.bf16.bf16.f32 "               \
        "{%0,%1,%2,%3},{%4,%5,%6,%7},{%8,%9},{%0,%1,%2,%3};"                 \
        : "+f"((D)[0]), "+f"((D)[1]), "+f"((D)[2]), "+f"((D)[3])             \
        : "r"((A)[0]), "r"((A)[1]), "r"((A)[2]), "r"((A)[3]),                \
          "r"((B)[0]), "r"((B)[1]))

__global__ void __launch_bounds__(256) k_gemm1(const float* __restrict__ x,
                                               const float* __restrict__ W1,
                                               const float* __restrict__ b1,
                                               const float* __restrict__ attl,
                                               const float* __restrict__ attr) {
    __shared__ __nv_bfloat16 As[2][128 * LDA];
    __shared__ __nv_bfloat16 Bs[2][128 * LDA];
    __shared__ float sal[128], sar[128];
    int tid = threadIdx.x;
    int lane = tid & 31;
    int wid = tid >> 5;
    int wm = wid >> 2;
    int wn = wid & 3;
    int rowBlk = blockIdx.x * 128;

    float c[4][4][4];
#pragma unroll
    for (int tm = 0; tm < 4; tm++)
#pragma unroll
        for (int tn = 0; tn < 4; tn++)
#pragma unroll
            for (int q = 0; q < 4; q++) c[tm][tn][q] = 0.f;

    if (tid < 128) { sal[tid] = 0.f; sar[tid] = 0.f; }

    float4 ra[4], rb[4];

#pragma unroll
    for (int u = 0; u < 4; u++) {
        int s = tid + u * 256;
        int r = s >> 3, q = s & 7;
        int gr = rowBlk + r;
        ra[u] = (gr < Nn) ? *(const float4*)(x + (size_t)gr * Fdim + q * 4)
                          : make_float4(0.f, 0.f, 0.f, 0.f);
        rb[u] = *(const float4*)(W1 + (size_t)r * Fdim + q * 4);
    }
#pragma unroll
    for (int u = 0; u < 4; u++) {
        int s = tid + u * 256;
        int r = s >> 3, q = s & 7;
        __nv_bfloat162 a0 = __floats2bfloat162_rn(ra[u].x, ra[u].y);
        __nv_bfloat162 a1 = __floats2bfloat162_rn(ra[u].z, ra[u].w);
        uint2 pk; pk.x = *(unsigned*)&a0; pk.y = *(unsigned*)&a1;
        *(uint2*)&As[0][r * LDA + q * 4] = pk;
        __nv_bfloat162 b0 = __floats2bfloat162_rn(rb[u].x, rb[u].y);
        __nv_bfloat162 b1v = __floats2bfloat162_rn(rb[u].z, rb[u].w);
        uint2 qk; qk.x = *(unsigned*)&b0; qk.y = *(unsigned*)&b1v;
        *(uint2*)&Bs[0][r * LDA + q * 4] = qk;
    }
    __syncthreads();

    unsigned as0 = (unsigned)__cvta_generic_to_shared(&As[0][0]);
    unsigned bs0 = (unsigned)__cvta_generic_to_shared(&Bs[0][0]);
    const unsigned bufstride = 128 * LDA * 2;

#pragma unroll 1
    for (int kt = 0; kt < 16; kt++) {
        int buf = kt & 1;
        if (kt < 15) {
            int k0 = (kt + 1) * 32;
#pragma unroll
            for (int u = 0; u < 4; u++) {
                int s = tid + u * 256;
                int r = s >> 3, q = s & 7;
                int gr = rowBlk + r;
                ra[u] = (gr < Nn)
                            ? *(const float4*)(x + (size_t)gr * Fdim + k0 + q * 4)
                            : make_float4(0.f, 0.f, 0.f, 0.f);
                rb[u] = *(const float4*)(W1 + (size_t)r * Fdim + k0 + q * 4);
            }
        }

        unsigned as_base = as0 + buf * bufstride;
        unsigned bs_base = bs0 + buf * bufstride;
#pragma unroll
        for (int s16 = 0; s16 < 2; s16++) {
            int kb = s16 * 16;
            unsigned a[4][4];
            int arow = wm * 64 + (lane & 15);
            int acol = kb + ((lane >> 4) << 3);
#pragma unroll
            for (int tm = 0; tm < 4; tm++) {
                unsigned addr = as_base + ((arow + tm * 16) * LDA + acol) * 2;
                LDSM4(a[tm][0], a[tm][1], a[tm][2], a[tm][3], addr);
            }
            unsigned b[4][2];
#pragma unroll
            for (int g = 0; g < 2; g++) {
                int nrow = wn * 32 + g * 16 + ((lane >> 4) & 1) * 8 + (lane & 7);
                int ncol = kb + ((lane >> 3) & 1) * 8;
                unsigned addr = bs_base + (nrow * LDA + ncol) * 2;
                unsigned r0, r1, r2, r3;
                LDSM4(r0, r1, r2, r3, addr);
                b[2 * g][0] = r0; b[2 * g][1] = r1;
                b[2 * g + 1][0] = r2; b[2 * g + 1][1] = r3;
            }
#pragma unroll
            for (int tm = 0; tm < 4; tm++)
#pragma unroll
                for (int tn = 0; tn < 4; tn++) MMA_BF16(c[tm][tn], a[tm], b[tn]);
        }

        if (kt < 15) {
            int nbuf = buf ^ 1;
#pragma unroll
            for (int u = 0; u < 4; u++) {
                int s = tid + u * 256;
                int r = s >> 3, q = s & 7;
                __nv_bfloat162 a0 = __floats2bfloat162_rn(ra[u].x, ra[u].y);
                __nv_bfloat162 a1 = __floats2bfloat162_rn(ra[u].z, ra[u].w);
                uint2 pk; pk.x = *(unsigned*)&a0; pk.y = *(unsigned*)&a1;
                *(uint2*)&As[nbuf][r * LDA + q * 4] = pk;
                __nv_bfloat162 b0 = __floats2bfloat162_rn(rb[u].x, rb[u].y);
                __nv_bfloat162 b1v = __floats2bfloat162_rn(rb[u].z, rb[u].w);
                uint2 qk; qk.x = *(unsigned*)&b0; qk.y = *(unsigned*)&b1v;
                *(uint2*)&Bs[nbuf][r * LDA + q * 4] = qk;
            }
        }
        __syncthreads();
    }

    // epilogue: bias + relu -> g_raw + g_h16A; fused layer-0 att reduction
    int r_base = rowBlk + wm * 64 + (lane >> 2);
#pragma unroll
    for (int tm = 0; tm < 4; tm++) {
#pragma unroll
        for (int half = 0; half < 2; half++) {
            int row = r_base + tm * 16 + half * 8;
            float pa = 0.f, pr = 0.f;
#pragma unroll
            for (int tn = 0; tn < 4; tn++) {
                int n = wn * 32 + tn * 8 + (lane & 3) * 2;
                float2 bv = *(const float2*)(b1 + n);
                float o0 = fmaxf(c[tm][tn][2 * half + 0] + bv.x, 0.f);
                float o1 = fmaxf(c[tm][tn][2 * half + 1] + bv.y, 0.f);
                float2 Lv = *(const float2*)(attl + n);
                float2 Rv = *(const float2*)(attr + n);
                pa += o0 * Lv.x + o1 * Lv.y;
                pr += o0 * Rv.x + o1 * Rv.y;
                if (row < Nn) {
                    *(float2*)(g_raw + (size_t)row * Hdim + n) =
                        make_float2(o0, o1);
                    g_h16A[(size_t)row * 64 + (n >> 1)] =
                        __floats2half2_rn(o0, o1);
                }
            }
            pa += __shfl_xor_sync(0xffffffffu, pa, 1);
            pa += __shfl_xor_sync(0xffffffffu, pa, 2);
            pr += __shfl_xor_sync(0xffffffffu, pr, 1);
            pr += __shfl_xor_sync(0xffffffffu, pr, 2);
            if ((lane & 3) == 0) {
                int rl = wm * 64 + tm * 16 + half * 8 + (lane >> 2);
                atomicAdd(&sal[rl], pa);
                atomicAdd(&sar[rl], pr);
            }
        }
    }
    __syncthreads();
    if (tid < 128) {
        int gr = rowBlk + tid;
        if (gr < Nn) { g_al[0][gr] = sal[tid]; g_ar[0][gr] = sar[tid]; }
    }
}

// ---------------- aggregation: warp/node, smem-staged coef, fused att/out ---
__global__ void k_agg(int h16in_sel, int h16out_sel, int rd, int wr,
                      const float* __restrict__ attl_next,
                      const float* __restrict__ attr_next, int write_att,
                      const float* __restrict__ W2, const float* __restrict__ b2,
                      float* __restrict__ out, int write_out) {
    __shared__ float slog[8][40];
    __shared__ int2 sedge[8][32];
    int gw = (blockIdx.x * blockDim.x + threadIdx.x) >> 5;
    int lane = threadIdx.x & 31;
    int lw = threadIdx.x >> 5;
    if (gw >= Nn) return;
    const uint2* h16v = (const uint2*)h16_sel(h16in_sel);
    const float* alr = g_al[rd];

    float4 acc = make_float4(0.f, 0.f, 0.f, 0.f);
    float ar_i = g_ar[rd][gw];
    int start = g_rowptr[gw];
    int end = g_rowptr[gw + 1];

    for (int base = start; base < end; base += 32) {
        int m = min(32, end - base);
        __syncwarp();
        if (lane < m) {
            int2 ed = g_edge[base + lane];
            float cf = tanhf(alr[ed.x] + ar_i) * __int_as_float(ed.y);
            sedge[lw][lane] = make_int2(ed.x, __float_as_int(cf));
        }
        __syncwarp();
#pragma unroll 4
        for (int j = 0; j < m; j++) {
            int2 ec = sedge[lw][j];
            float c = __int_as_float(ec.y);
            uint2 hv = h16v[(size_t)ec.x * 32 + lane];
            float2 f0 = __half22float2(*(__half2*)&hv.x);
            float2 f1 = __half22float2(*(__half2*)&hv.y);
            acc.x = fmaf(c, f0.x, acc.x);
            acc.y = fmaf(c, f0.y, acc.y);
            acc.z = fmaf(c, f1.x, acc.z);
            acc.w = fmaf(c, f1.y, acc.w);
        }
    }

    // self loop (fp16 state) + eps*raw (fp32)
    float d = g_dis[gw];
    float cs = tanhf(alr[gw] + ar_i) * d * d;
    uint2 hvs = h16v[(size_t)gw * 32 + lane];
    float2 s0 = __half22float2(*(__half2*)&hvs.x);
    float2 s1 = __half22float2(*(__half2*)&hvs.y);
    float4 rw = ((const float4*)g_raw)[(size_t)gw * 32 + lane];
    acc.x += cs * s0.x + EPSv * rw.x;
    acc.y += cs * s0.y + EPSv * rw.y;
    acc.z += cs * s1.x + EPSv * rw.z;
    acc.w += cs * s1.y + EPSv * rw.w;

    if (!write_out) {
        __half2 hh[2];
        hh[0] = __floats2half2_rn(acc.x, acc.y);
        hh[1] = __floats2half2_rn(acc.z, acc.w);
        ((uint2*)h16_sel(h16out_sel))[(size_t)gw * 32 + lane] = *(uint2*)hh;
    }

    if (write_att) {
        float4 Lv = ((const float4*)attl_next)[lane];
        float4 Rv = ((const float4*)attr_next)[lane];
        float pa = acc.x * Lv.x + acc.y * Lv.y + acc.z * Lv.z + acc.w * Lv.w;
        float pr = acc.x * Rv.x + acc.y * Rv.y + acc.z * Rv.z + acc.w * Rv.w;
#pragma unroll
        for (int off = 16; off; off >>= 1) {
            pa += __shfl_xor_sync(0xffffffffu, pa, off);
            pr += __shfl_xor_sync(0xffffffffu, pr, off);
        }
        if (lane == 0) { g_al[wr][gw] = pa; g_ar[wr][gw] = pr; }
    }

    if (write_out) {
#pragma unroll
        for (int c = 0; c < Cdim; c++) {
            float4 wv = *(const float4*)(W2 + (size_t)c * Hdim + lane * 4);
            float p = acc.x * wv.x + acc.y * wv.y + acc.z * wv.z + acc.w * wv.w;
            p += __shfl_down_sync(0xffffffffu, p, 16);
            p += __shfl_down_sync(0xffffffffu, p, 8);
            p += __shfl_down_sync(0xffffffffu, p, 4);
            p += __shfl_down_sync(0xffffffffu, p, 2);
            p += __shfl_down_sync(0xffffffffu, p, 1);
            if (lane == 0) slog[lw][c] = p + b2[c];
        }
        __syncwarp();
        float m = -1e30f;
        for (int c = lane; c < Cdim; c += 32) m = fmaxf(m, slog[lw][c]);
#pragma unroll
        for (int o = 16; o; o >>= 1)
            m = fmaxf(m, __shfl_xor_sync(0xffffffffu, m, o));
        float s = 0.f;
        for (int c = lane; c < Cdim; c += 32) s += expf(slog[lw][c] - m);
#pragma unroll
        for (int o = 16; o; o >>= 1) s += __shfl_xor_sync(0xffffffffu, s, o);
        float lse = m + logf(s);
        for (int c = lane; c < Cdim; c += 32)
            out[(size_t)gw * Cdim + c] = slog[lw][c] - lse;
    }
}

// ---------------- launch: CSR || GEMM(+att0) fork, 4x agg, 9 launches -------
extern "C" void kernel_launch(void* const* d_in, const int* in_sizes, int n_in,
                              void* d_out, int out_size) {
    const float* x = (const float*)d_in[0];
    const int* ei = (const int*)d_in[1];
    const float* W1 = (const float*)d_in[2];
    const float* b1 = (const float*)d_in[3];
    const float* W2 = (const float*)d_in[4];
    const float* b2 = (const float*)d_in[5];
    const float* attl = (const float*)d_in[6];
    const float* attr = (const float*)d_in[7];
    float* out = (float*)d_out;

    const int NBn = (Nn + 255) / 256;
    const int NBe = (Ee + 255) / 256;
    const int NBw = (Nn * 32 + 255) / 256;

    cudaEventRecord(g_evFork, 0);
    cudaStreamWaitEvent(g_s2, g_evFork, 0);

    // side stream: GEMM with fused layer-0 att
    k_gemm1<<<(Nn + 127) / 128, 256, 0, g_s2>>>(x, W1, b1, attl, attr);

    // main stream: CSR build chain (g_cnt pre-zeroed by prior call's scan3)
    k_hist<<<NBe, 256>>>(ei, Ee);
    k_scan1<<<NBn, 256>>>(Nn);
    k_scan3<<<NBn, 256>>>(Nn, NBn);
    k_fill<<<NBe, 256>>>(ei, Ee);

    cudaEventRecord(g_evJoin, g_s2);
    cudaStreamWaitEvent(0, g_evJoin, 0);

    int h16in = 0;
    for (int l = 0; l < 4; l++) {
        int rd = l & 1;
        int wr = 1 - rd;
        int h16out = 1 - h16in;
        const float* al_n = (l < 3) ? attl + (l + 1) * Hdim : attl;
        const float* ar_n = (l < 3) ? attr + (l + 1) * Hdim : attr;
        k_agg<<<NBw, 256>>>(h16in, h16out, rd, wr, al_n, ar_n, l < 3 ? 1 : 0,
                            W2, b2, out, l == 3 ? 1 : 0);
        h16in = h16out;
    }
}